// round 1
// baseline (speedup 1.0000x reference)
#include <cuda_runtime.h>

#define TT 8
#define BB 16
#define CC 384
#define NN 1024
#define NHEAD 8
#define HD 48
#define NIMG 128
#define EPSF 1e-5f
#define YELEMS 50331648  /* 8*16*384*1024 */

// Scratch (allocation-free rule: __device__ globals)
__device__ float g_q[YELEMS];  // q activations, conv layout [img][C][N]
__device__ float g_k[YELEMS];  // k activations, conv layout
__device__ float g_o[YELEMS];  // relu(attention out), conv layout

// ---------------------------------------------------------------------------
// Kernel 1: QKV conv1x1 GEMM + BN + ReLU.
//   out[o,n] = relu(bn(sum_c w[o,c] * relu(x[c,n])))
//   q,k -> scratch in conv layout; v -> d_out v-region in [T,B,h,N,d] layout.
// Block tile 128(M) x 128(N), K-chunk 8, 256 threads, 8x8 per-thread tile
// arranged as 2x2 blocks of 4x4 for conflict-free float4 SMEM access.
// ---------------------------------------------------------------------------
__global__ __launch_bounds__(256) void qkv_kernel(
    const float* __restrict__ x,
    const float* __restrict__ qw, const float* __restrict__ qbn,
    const float* __restrict__ kw, const float* __restrict__ kbn,
    const float* __restrict__ vw, const float* __restrict__ vbn,
    float* __restrict__ vout)
{
    __shared__ __align__(16) float ws[8][128];
    __shared__ __align__(16) float xs[8][128];

    const int tid  = threadIdx.x;
    const int img  = blockIdx.z;                 // t*16+b
    const int mt   = blockIdx.y;                 // 0..8 (3 tiles x 3 matrices)
    const int nt   = blockIdx.x * 128;
    const int mat  = mt / 3;                     // 0=q,1=k,2=v
    const int mloc = (mt % 3) * 128;

    const float* wptr = (mat == 0) ? qw : ((mat == 1) ? kw : vw);
    const float* bnp  = (mat == 0) ? qbn : ((mat == 1) ? kbn : vbn);
    const float* xb   = x + (size_t)img * (CC * NN);

    const int tx = tid & 15, ty = tid >> 4;

    float acc[8][8];
#pragma unroll
    for (int i = 0; i < 8; i++)
#pragma unroll
        for (int j = 0; j < 8; j++) acc[i][j] = 0.f;

    const int wm = tid >> 1;            // 0..127 (output channel within tile)
    const int wk = (tid & 1) * 4;       // 0 or 4
    const int xk = tid >> 5;            // 0..7
    const int xn = (tid & 31) * 4;      // 0..124

    const float* wload = wptr + (size_t)(mloc + wm) * CC + wk;
    const float* xload = xb + (size_t)xk * NN + nt + xn;

    for (int kt = 0; kt < CC; kt += 8) {
        float4 wv = *(const float4*)(wload + kt);
        float4 xv = *(const float4*)(xload + (size_t)kt * NN);
        ws[wk + 0][wm] = wv.x; ws[wk + 1][wm] = wv.y;
        ws[wk + 2][wm] = wv.z; ws[wk + 3][wm] = wv.w;
        xv.x = fmaxf(xv.x, 0.f); xv.y = fmaxf(xv.y, 0.f);
        xv.z = fmaxf(xv.z, 0.f); xv.w = fmaxf(xv.w, 0.f);
        *(float4*)&xs[xk][xn] = xv;
        __syncthreads();
#pragma unroll
        for (int k = 0; k < 8; k++) {
            float a[8], bv[8];
            float4 t0 = *(const float4*)&ws[k][ty * 4];
            float4 t1 = *(const float4*)&ws[k][64 + ty * 4];
            a[0] = t0.x; a[1] = t0.y; a[2] = t0.z; a[3] = t0.w;
            a[4] = t1.x; a[5] = t1.y; a[6] = t1.z; a[7] = t1.w;
            float4 u0 = *(const float4*)&xs[k][tx * 4];
            float4 u1 = *(const float4*)&xs[k][64 + tx * 4];
            bv[0] = u0.x; bv[1] = u0.y; bv[2] = u0.z; bv[3] = u0.w;
            bv[4] = u1.x; bv[5] = u1.y; bv[6] = u1.z; bv[7] = u1.w;
#pragma unroll
            for (int i = 0; i < 8; i++)
#pragma unroll
                for (int j = 0; j < 8; j++) acc[i][j] += a[i] * bv[j];
        }
        __syncthreads();
    }

    // Epilogue: BN + ReLU, store.
#pragma unroll
    for (int i = 0; i < 8; i++) {
        const int m = (i < 4) ? (ty * 4 + i) : (64 + ty * 4 + (i - 4));
        const int c = mloc + m;                          // channel 0..383
        const float ga = bnp[c], be = bnp[CC + c];
        const float mn = bnp[2 * CC + c], vr = bnp[3 * CC + c];
        const float inv = ga * rsqrtf(vr + EPSF);
        const float off = be - mn * inv;
        float r[8];
#pragma unroll
        for (int j = 0; j < 8; j++) r[j] = fmaxf(acc[i][j] * inv + off, 0.f);

        if (mat == 2) {
            // v output: [T,B,h,N,d] with d = c%48, h = c/48
            const int hh = c / HD, dd = c % HD;
            float* vbase = vout + ((size_t)(img * NHEAD + hh)) * NN * HD + dd;
#pragma unroll
            for (int j = 0; j < 8; j++) {
                const int n = nt + ((j < 4) ? (tx * 4 + j) : (64 + tx * 4 + (j - 4)));
                vbase[(size_t)n * HD] = r[j];
            }
        } else {
            float* dst = (mat == 0 ? g_q : g_k)
                         + (size_t)img * (CC * NN) + (size_t)c * NN + nt;
            *(float4*)(dst + tx * 4)      = make_float4(r[0], r[1], r[2], r[3]);
            *(float4*)(dst + 64 + tx * 4) = make_float4(r[4], r[5], r[6], r[7]);
        }
    }
}

// ---------------------------------------------------------------------------
// Kernel 2: chunked linear attention, one block per (nc, b, h) group.
//   A[d,e] = scale * sum_{s<2048} k[s,d] v[s,e]   (phase A, 3x3 reg tiles)
//   out[s,e] = relu(sum_d q[s,d] A[d,e])          (phase B, 2 s-rows/thread)
// ---------------------------------------------------------------------------
__global__ __launch_bounds__(256, 2) void attn_kernel(const float* __restrict__ vout)
{
    __shared__ __align__(16) float ks[32][49];   // padded: conflict-free stores
    __shared__ __align__(16) float vs[32][48];
    __shared__ __align__(16) float at[48][48];

    const int tid = threadIdx.x;
    const int g   = blockIdx.x;
    const int nc  = g >> 7;
    const int b   = (g >> 3) & 15;
    const int h   = g & 7;
    const int tx  = tid & 15, ty = tid >> 4;
    const int d0  = ty * 3, e0 = tx * 3;

    float a9[9];
#pragma unroll
    for (int i = 0; i < 9; i++) a9[i] = 0.f;

    for (int st = 0; st < 2048; st += 32) {
        const int t  = nc * 2 + (st >> 10);
        const int n0 = st & 1023;
        const float* kb = g_k + ((size_t)(t * BB + b) * CC + h * HD) * NN + n0;
        const float* vb = vout + (((size_t)((t * BB + b) * NHEAD + h)) * NN + n0) * HD;
#pragma unroll
        for (int i = 0; i < 6; i++) {
            const int idx = i * 256 + tid;                 // 0..1535
            ks[idx & 31][idx >> 5] = kb[(size_t)(idx >> 5) * NN + (idx & 31)];
            vs[idx / 48][idx % 48] = vb[idx];              // contiguous [sl][d]
        }
        __syncthreads();
#pragma unroll
        for (int sl = 0; sl < 32; sl++) {
            const float k0 = ks[sl][d0], k1 = ks[sl][d0 + 1], k2 = ks[sl][d0 + 2];
            const float v0 = vs[sl][e0], v1 = vs[sl][e0 + 1], v2 = vs[sl][e0 + 2];
            a9[0] += k0 * v0; a9[1] += k0 * v1; a9[2] += k0 * v2;
            a9[3] += k1 * v0; a9[4] += k1 * v1; a9[5] += k1 * v2;
            a9[6] += k2 * v0; a9[7] += k2 * v1; a9[8] += k2 * v2;
        }
        __syncthreads();
    }

    const float scale = 1.f / 32.f;
#pragma unroll
    for (int i = 0; i < 3; i++)
#pragma unroll
        for (int j = 0; j < 3; j++) at[d0 + i][e0 + j] = a9[i * 3 + j] * scale;
    __syncthreads();

    // Phase B: two s-rows per thread per pass (amortize SMEM broadcasts)
    for (int sb = 0; sb < 2048; sb += 512) {
        const int s0 = sb + tid;
        const int s1 = sb + 256 + tid;
        const int t0 = nc * 2 + (s0 >> 10), m0 = s0 & 1023;
        const int t1 = nc * 2 + (s1 >> 10), m1 = s1 & 1023;
        const float* q0 = g_q + ((size_t)(t0 * BB + b) * CC + h * HD) * NN + m0;
        const float* q1 = g_q + ((size_t)(t1 * BB + b) * CC + h * HD) * NN + m1;
        float o0[48], o1[48];
#pragma unroll
        for (int e = 0; e < 48; e++) { o0[e] = 0.f; o1[e] = 0.f; }
#pragma unroll 4
        for (int d = 0; d < 48; d++) {
            const float qa = q0[(size_t)d * NN];
            const float qb = q1[(size_t)d * NN];
            const float4* ar = (const float4*)&at[d][0];
#pragma unroll
            for (int e4 = 0; e4 < 12; e4++) {
                const float4 av = ar[e4];
                o0[e4 * 4 + 0] += qa * av.x; o0[e4 * 4 + 1] += qa * av.y;
                o0[e4 * 4 + 2] += qa * av.z; o0[e4 * 4 + 3] += qa * av.w;
                o1[e4 * 4 + 0] += qb * av.x; o1[e4 * 4 + 1] += qb * av.y;
                o1[e4 * 4 + 2] += qb * av.z; o1[e4 * 4 + 3] += qb * av.w;
            }
        }
        float* p0 = g_o + ((size_t)(t0 * BB + b) * CC + h * HD) * NN + m0;
        float* p1 = g_o + ((size_t)(t1 * BB + b) * CC + h * HD) * NN + m1;
#pragma unroll
        for (int e = 0; e < 48; e++) {
            p0[(size_t)e * NN] = fmaxf(o0[e], 0.f);
            p1[(size_t)e * NN] = fmaxf(o1[e], 0.f);
        }
    }
}

// ---------------------------------------------------------------------------
// Kernel 3: proj conv1x1 GEMM + bias + BN + identity add -> y output.
// Same GEMM structure as kernel 1 (input already ReLU'd in kernel 2).
// ---------------------------------------------------------------------------
__global__ __launch_bounds__(256) void proj_kernel(
    const float* __restrict__ x,
    const float* __restrict__ pw, const float* __restrict__ pb,
    const float* __restrict__ pbn,
    float* __restrict__ yout)
{
    __shared__ __align__(16) float ws[8][128];
    __shared__ __align__(16) float xs[8][128];

    const int tid  = threadIdx.x;
    const int img  = blockIdx.z;
    const int nt   = blockIdx.x * 128;
    const int mloc = blockIdx.y * 128;

    const float* ib = g_o + (size_t)img * (CC * NN);
    const int tx = tid & 15, ty = tid >> 4;

    float acc[8][8];
#pragma unroll
    for (int i = 0; i < 8; i++)
#pragma unroll
        for (int j = 0; j < 8; j++) acc[i][j] = 0.f;

    const int wm = tid >> 1;
    const int wk = (tid & 1) * 4;
    const int xk = tid >> 5;
    const int xn = (tid & 31) * 4;

    const float* wload = pw + (size_t)(mloc + wm) * CC + wk;
    const float* xload = ib + (size_t)xk * NN + nt + xn;

    for (int kt = 0; kt < CC; kt += 8) {
        float4 wv = *(const float4*)(wload + kt);
        float4 xv = *(const float4*)(xload + (size_t)kt * NN);
        ws[wk + 0][wm] = wv.x; ws[wk + 1][wm] = wv.y;
        ws[wk + 2][wm] = wv.z; ws[wk + 3][wm] = wv.w;
        *(float4*)&xs[xk][xn] = xv;
        __syncthreads();
#pragma unroll
        for (int k = 0; k < 8; k++) {
            float a[8], bv[8];
            float4 t0 = *(const float4*)&ws[k][ty * 4];
            float4 t1 = *(const float4*)&ws[k][64 + ty * 4];
            a[0] = t0.x; a[1] = t0.y; a[2] = t0.z; a[3] = t0.w;
            a[4] = t1.x; a[5] = t1.y; a[6] = t1.z; a[7] = t1.w;
            float4 u0 = *(const float4*)&xs[k][tx * 4];
            float4 u1 = *(const float4*)&xs[k][64 + tx * 4];
            bv[0] = u0.x; bv[1] = u0.y; bv[2] = u0.z; bv[3] = u0.w;
            bv[4] = u1.x; bv[5] = u1.y; bv[6] = u1.z; bv[7] = u1.w;
#pragma unroll
            for (int i = 0; i < 8; i++)
#pragma unroll
                for (int j = 0; j < 8; j++) acc[i][j] += a[i] * bv[j];
        }
        __syncthreads();
    }

#pragma unroll
    for (int i = 0; i < 8; i++) {
        const int m = (i < 4) ? (ty * 4 + i) : (64 + ty * 4 + (i - 4));
        const int c = mloc + m;
        const float ga = pbn[c], be = pbn[CC + c];
        const float mn = pbn[2 * CC + c], vr = pbn[3 * CC + c];
        const float inv  = ga * rsqrtf(vr + EPSF);
        const float off  = be - mn * inv;
        const float bias = pb[c];

        const float* xid = x + (size_t)img * (CC * NN) + (size_t)c * NN + nt;
        float* yb = yout + (size_t)img * (CC * NN) + (size_t)c * NN + nt;

        float4 xi0 = *(const float4*)(xid + tx * 4);
        float4 xi1 = *(const float4*)(xid + 64 + tx * 4);
        float4 o0, o1;
        o0.x = (acc[i][0] + bias) * inv + off + xi0.x;
        o0.y = (acc[i][1] + bias) * inv + off + xi0.y;
        o0.z = (acc[i][2] + bias) * inv + off + xi0.z;
        o0.w = (acc[i][3] + bias) * inv + off + xi0.w;
        o1.x = (acc[i][4] + bias) * inv + off + xi1.x;
        o1.y = (acc[i][5] + bias) * inv + off + xi1.y;
        o1.z = (acc[i][6] + bias) * inv + off + xi1.z;
        o1.w = (acc[i][7] + bias) * inv + off + xi1.w;
        *(float4*)(yb + tx * 4)      = o0;
        *(float4*)(yb + 64 + tx * 4) = o1;
    }
}

// ---------------------------------------------------------------------------
extern "C" void kernel_launch(void* const* d_in, const int* in_sizes, int n_in,
                              void* d_out, int out_size)
{
    (void)in_sizes; (void)n_in; (void)out_size;
    const float* x   = (const float*)d_in[0];
    const float* qw  = (const float*)d_in[1];
    const float* qbn = (const float*)d_in[2];
    const float* kw  = (const float*)d_in[3];
    const float* kbn = (const float*)d_in[4];
    const float* vw  = (const float*)d_in[5];
    const float* vbn = (const float*)d_in[6];
    const float* pw  = (const float*)d_in[7];
    const float* pb  = (const float*)d_in[8];
    const float* pbn = (const float*)d_in[9];

    float* y = (float*)d_out;             // first output: y
    float* v = (float*)d_out + YELEMS;    // second output: v

    dim3 g1(8, 9, NIMG);
    qkv_kernel<<<g1, 256>>>(x, qw, qbn, kw, kbn, vw, vbn, v);

    attn_kernel<<<512, 256>>>(v);

    dim3 g3(8, 3, NIMG);
    proj_kernel<<<g3, 256>>>(x, pw, pb, pbn, y);
}